// round 2
// baseline (speedup 1.0000x reference)
#include <cuda_runtime.h>
#include <cstdint>

// Problem constants
#define B_SZ   4
#define C_IN   512
#define TD     512
#define HW     4096
#define HH     64
#define WW     64
#define NCH3   1536          // 3*td
#define GROUPS 192
#define NHEAD  128           // 3072/24
#define EPSF   1e-15f

// ---------------- scratch (static device globals; no runtime alloc) ----------------
__device__ float g_qkv [(long)B_SZ * NCH3 * HW];
__device__ float g_agg [(long)B_SZ * NCH3 * HW];
__device__ float g_outn[(long)B_SZ * 1024 * HW];
__device__ float g_vk  [B_SZ * NHEAD * 72];

// ---------------- tf32 mma helpers ----------------
__device__ __forceinline__ uint32_t f2tf32(float f) {
    uint32_t r; asm("cvt.rna.tf32.f32 %0, %1;" : "=r"(r) : "f"(f)); return r;
}
__device__ __forceinline__ void mma_tf32(float (&c)[4], const uint32_t (&a)[4], const uint32_t (&b)[2]) {
    asm volatile(
        "mma.sync.aligned.m16n8k8.row.col.f32.tf32.tf32.f32 "
        "{%0,%1,%2,%3}, {%4,%5,%6,%7}, {%8,%9}, {%0,%1,%2,%3};\n"
        : "+f"(c[0]), "+f"(c[1]), "+f"(c[2]), "+f"(c[3])
        : "r"(a[0]), "r"(a[1]), "r"(a[2]), "r"(a[3]), "r"(b[0]), "r"(b[1]));
}

// ---------------- GEMM: C[b] = W[M,K] * X[b][K,N] (+ optional addend), tf32 ----------------
// BM=128, BN=64, BK=16; 256 threads = 8 warps, warp grid 4(m) x 2(n), warp tile 32x32.
// Smem holds pre-converted tf32 (u32). Double-buffered; 1 sync per K-step.
#define GBM 128
#define GBN 64
#define GBK 16
#define ASTR (GBM + 8)   // 136: frag-load banks = 8t + g + const, all distinct
#define BSTR (GBN + 8)   // 72 : same property

__global__ void __launch_bounds__(256)
gemm_tf32_kernel(const float* __restrict__ Wm, const float* __restrict__ Xm,
                 float* __restrict__ Cm, const float* __restrict__ Addend,
                 int M, int K, int N)
{
    __shared__ uint32_t As[2][GBK][ASTR];
    __shared__ uint32_t Bs[2][GBK][BSTR];

    int b  = blockIdx.z;
    const float* Xb = Xm + (long)b * K * N;
    float*       Cb = Cm + (long)b * M * N;
    const float* Ab = Addend ? (Addend + (long)b * M * N) : nullptr;

    int m0 = blockIdx.y * GBM;
    int n0 = blockIdx.x * GBN;

    int tid  = threadIdx.x;
    int lane = tid & 31, warp = tid >> 5;
    int wm = warp >> 1;          // 0..3
    int wn = warp & 1;           // 0..1
    int g = lane >> 2, t = lane & 3;

    // A-load mapping: idx = tid + 256r -> m = idx&127 (warp-consecutive -> conflict-free STS),
    // kq = (idx>>7)*4 (one float4 of K per thread)
    int am0 = tid & 127,        ak0 = (tid >> 7) * 4;
    int am1 = am0,              ak1 = ak0 + 8;      // idx+256 flips bit 8 of (idx>>7)*4
    // B-load mapping: one float4 of N per thread
    int bk = tid >> 4, bn = (tid & 15) * 4;

    const float* Aptr0 = &Wm[(long)(m0 + am0) * K + ak0];
    const float* Aptr1 = &Wm[(long)(m0 + am1) * K + ak1];
    const float* Bptr  = &Xb[(long)bk * N + n0 + bn];

    float acc[2][4][4];
#pragma unroll
    for (int i = 0; i < 2; i++)
#pragma unroll
        for (int j = 0; j < 4; j++)
#pragma unroll
            for (int q = 0; q < 4; q++) acc[i][j][q] = 0.f;

    float4 aR0, aR1, bR;

    // prologue: tile 0
    aR0 = *(const float4*)(Aptr0);
    aR1 = *(const float4*)(Aptr1);
    bR  = *(const float4*)(Bptr);
    {
        As[0][ak0 + 0][am0] = f2tf32(aR0.x); As[0][ak0 + 1][am0] = f2tf32(aR0.y);
        As[0][ak0 + 2][am0] = f2tf32(aR0.z); As[0][ak0 + 3][am0] = f2tf32(aR0.w);
        As[0][ak1 + 0][am1] = f2tf32(aR1.x); As[0][ak1 + 1][am1] = f2tf32(aR1.y);
        As[0][ak1 + 2][am1] = f2tf32(aR1.z); As[0][ak1 + 3][am1] = f2tf32(aR1.w);
        uint4 bv = make_uint4(f2tf32(bR.x), f2tf32(bR.y), f2tf32(bR.z), f2tf32(bR.w));
        *(uint4*)&Bs[0][bk][bn] = bv;
    }
    __syncthreads();

    int KT = K / GBK;
    for (int kt = 0; kt < KT; kt++) {
        int p = kt & 1;
        if (kt + 1 < KT) {
            long ko = (long)(kt + 1) * GBK;
            aR0 = *(const float4*)(Aptr0 + ko);
            aR1 = *(const float4*)(Aptr1 + ko);
            bR  = *(const float4*)(Bptr + ko * N);
        }

#pragma unroll
        for (int k8 = 0; k8 < GBK; k8 += 8) {
            uint32_t af[2][4], bf[4][2];
#pragma unroll
            for (int mt = 0; mt < 2; mt++) {
                int mr = wm * 32 + mt * 16 + g;
                af[mt][0] = As[p][k8 + t    ][mr    ];
                af[mt][1] = As[p][k8 + t    ][mr + 8];
                af[mt][2] = As[p][k8 + t + 4][mr    ];
                af[mt][3] = As[p][k8 + t + 4][mr + 8];
            }
#pragma unroll
            for (int nt = 0; nt < 4; nt++) {
                int nc = wn * 32 + nt * 8 + g;
                bf[nt][0] = Bs[p][k8 + t    ][nc];
                bf[nt][1] = Bs[p][k8 + t + 4][nc];
            }
#pragma unroll
            for (int mt = 0; mt < 2; mt++)
#pragma unroll
                for (int nt = 0; nt < 4; nt++)
                    mma_tf32(acc[mt][nt], af[mt], bf[nt]);
        }

        if (kt + 1 < KT) {
            int q = p ^ 1;
            As[q][ak0 + 0][am0] = f2tf32(aR0.x); As[q][ak0 + 1][am0] = f2tf32(aR0.y);
            As[q][ak0 + 2][am0] = f2tf32(aR0.z); As[q][ak0 + 3][am0] = f2tf32(aR0.w);
            As[q][ak1 + 0][am1] = f2tf32(aR1.x); As[q][ak1 + 1][am1] = f2tf32(aR1.y);
            As[q][ak1 + 2][am1] = f2tf32(aR1.z); As[q][ak1 + 3][am1] = f2tf32(aR1.w);
            uint4 bv = make_uint4(f2tf32(bR.x), f2tf32(bR.y), f2tf32(bR.z), f2tf32(bR.w));
            *(uint4*)&Bs[q][bk][bn] = bv;
            __syncthreads();
        }
    }

    // Epilogue
#pragma unroll
    for (int mt = 0; mt < 2; mt++) {
#pragma unroll
        for (int nt = 0; nt < 4; nt++) {
            int row = m0 + wm * 32 + mt * 16 + g;
            int col = n0 + wn * 32 + nt * 8 + 2 * t;
            float2 v0 = make_float2(acc[mt][nt][0], acc[mt][nt][1]);
            float2 v1 = make_float2(acc[mt][nt][2], acc[mt][nt][3]);
            long o0 = (long)row * N + col;
            long o1 = (long)(row + 8) * N + col;
            if (Ab) {
                float2 a0 = *(const float2*)&Ab[o0];
                float2 a1 = *(const float2*)&Ab[o1];
                v0.x += a0.x; v0.y += a0.y;
                v1.x += a1.x; v1.y += a1.y;
            }
            *(float2*)&Cb[o0] = v0;
            *(float2*)&Cb[o1] = v1;
        }
    }
}

// ---------------- fused depthwise 5x5 + grouped pointwise 8x8 ----------------
__global__ void __launch_bounds__(256)
dwpw_kernel(const float* __restrict__ qkv, const float* __restrict__ w_dw,
            const float* __restrict__ w_pw, float* __restrict__ agg)
{
    __shared__ float in_s[36][36];
    __shared__ float dw_s[8][1024];
    __shared__ float wpw_s[64];

    int tid = threadIdx.x;
    int tb  = blockIdx.x;
    int x0  = (tb & 1) * 32;
    int y0  = (tb >> 1) * 32;
    int grp = blockIdx.y;
    int b   = blockIdx.z;

    if (tid < 64) wpw_s[tid] = w_pw[(grp * 8 + (tid >> 3)) * 8 + (tid & 7)];

    for (int c = 0; c < 8; c++) {
        int ch = grp * 8 + c;
        const float* src = qkv + ((long)b * NCH3 + ch) * HW;
        __syncthreads();
        for (int i = tid; i < 36 * 36; i += 256) {
            int r = i / 36, cc = i % 36;
            int gy = y0 + r - 2, gx = x0 + cc - 2;
            float v = 0.f;
            if (gy >= 0 && gy < HH && gx >= 0 && gx < WW)
                v = src[gy * WW + gx];
            in_s[r][cc] = v;
        }
        float wreg[25];
#pragma unroll
        for (int j = 0; j < 25; j++) wreg[j] = __ldg(&w_dw[ch * 25 + j]);
        __syncthreads();
        for (int p = tid; p < 1024; p += 256) {
            int py = p >> 5, px = p & 31;
            float s = 0.f;
#pragma unroll
            for (int dy = 0; dy < 5; dy++)
#pragma unroll
                for (int dx = 0; dx < 5; dx++)
                    s += in_s[py + dy][px + dx] * wreg[dy * 5 + dx];
            dw_s[c][p] = s;
        }
    }
    __syncthreads();

    for (int p = tid; p < 1024; p += 256) {
        float din[8];
#pragma unroll
        for (int i = 0; i < 8; i++) din[i] = dw_s[i][p];
        int py = p >> 5, px = p & 31;
        long base = ((long)b * NCH3 + grp * 8) * HW + (long)(y0 + py) * WW + (x0 + px);
#pragma unroll
        for (int o = 0; o < 8; o++) {
            float s = 0.f;
#pragma unroll
            for (int i = 0; i < 8; i++) s += wpw_s[o * 8 + i] * din[i];
            agg[base + (long)o * HW] = s;
        }
    }
}

// ---------------- vk reduction ----------------
__global__ void __launch_bounds__(256)
vk_kernel(const float* __restrict__ qkv, const float* __restrict__ agg,
          float* __restrict__ vkout)
{
    int bh = blockIdx.x;
    int b = bh >> 7, h = bh & 127;
    const float* src = (h < 64)
        ? qkv + ((long)b * NCH3 + h * 24) * HW
        : agg + ((long)b * NCH3 + (h - 64) * 24) * HW;

    int tid = threadIdx.x, lane = tid & 31;
    float acc[72];
#pragma unroll
    for (int i = 0; i < 72; i++) acc[i] = 0.f;

    for (int n = tid; n < HW; n += 256) {
        float kv[8], vv[8];
#pragma unroll
        for (int e = 0; e < 8; e++) kv[e] = fmaxf(src[(long)(8 + e) * HW + n], 0.f);
#pragma unroll
        for (int d = 0; d < 8; d++) vv[d] = src[(long)(16 + d) * HW + n];
#pragma unroll
        for (int d = 0; d < 8; d++)
#pragma unroll
            for (int e = 0; e < 8; e++) acc[d * 8 + e] += vv[d] * kv[e];
#pragma unroll
        for (int e = 0; e < 8; e++) acc[64 + e] += kv[e];
    }
#pragma unroll
    for (int i = 0; i < 72; i++) {
#pragma unroll
        for (int off = 16; off > 0; off >>= 1)
            acc[i] += __shfl_xor_sync(0xFFFFFFFFu, acc[i], off);
    }
    __shared__ float red[72];
    if (tid < 72) red[tid] = 0.f;
    __syncthreads();
    if (lane == 0) {
#pragma unroll
        for (int i = 0; i < 72; i++) atomicAdd(&red[i], acc[i]);
    }
    __syncthreads();
    if (tid < 72) vkout[(long)bh * 72 + tid] = red[tid];
}

// ---------------- per-pixel attention output + normalization ----------------
__global__ void __launch_bounds__(256)
outnorm_kernel(const float* __restrict__ qkv, const float* __restrict__ agg,
               const float* __restrict__ vkin, float* __restrict__ outn)
{
    int bh = blockIdx.y;
    int b = bh >> 7, h = bh & 127;
    const float* src = (h < 64)
        ? qkv + ((long)b * NCH3 + h * 24) * HW
        : agg + ((long)b * NCH3 + (h - 64) * 24) * HW;

    __shared__ float vks[72];
    int tid = threadIdx.x;
    if (tid < 72) vks[tid] = vkin[(long)bh * 72 + tid];
    __syncthreads();

    int n = blockIdx.x * 256 + tid;
    float q[8];
#pragma unroll
    for (int e = 0; e < 8; e++) q[e] = fmaxf(src[(long)e * HW + n], 0.f);

    float den = 0.f;
#pragma unroll
    for (int e = 0; e < 8; e++) den += vks[64 + e] * q[e];
    float inv = 1.f / (den + EPSF);

    long obase = ((long)b * 1024 + h * 8) * HW + n;
#pragma unroll
    for (int d = 0; d < 8; d++) {
        float num = 0.f;
#pragma unroll
        for (int e = 0; e < 8; e++) num += vks[d * 8 + e] * q[e];
        outn[obase + (long)d * HW] = num * inv;
    }
}

// ---------------- launch ----------------
extern "C" void kernel_launch(void* const* d_in, const int* in_sizes, int n_in,
                              void* d_out, int out_size)
{
    const float* x      = (const float*)d_in[0];
    const float* w_qkv  = (const float*)d_in[1];
    const float* w_dw   = (const float*)d_in[2];
    const float* w_pw   = (const float*)d_in[3];
    const float* w_proj = (const float*)d_in[4];
    float* out = (float*)d_out;

    float *qkv_p, *agg_p, *outn_p, *vk_p;
    cudaGetSymbolAddress((void**)&qkv_p,  g_qkv);
    cudaGetSymbolAddress((void**)&agg_p,  g_agg);
    cudaGetSymbolAddress((void**)&outn_p, g_outn);
    cudaGetSymbolAddress((void**)&vk_p,   g_vk);

    // 1) qkv = W_qkv @ x   : M=1536, K=512, N=4096, per batch
    gemm_tf32_kernel<<<dim3(HW / GBN, NCH3 / GBM, B_SZ), 256>>>(
        w_qkv, x, qkv_p, nullptr, NCH3, C_IN, HW);

    // 2) agg = grouped_pw(depthwise5x5(qkv))
    dwpw_kernel<<<dim3(4, GROUPS, B_SZ), 256>>>(qkv_p, w_dw, w_pw, agg_p);

    // 3) vk[b,h] 9x8 reductions
    vk_kernel<<<B_SZ * NHEAD, 256>>>(qkv_p, agg_p, vk_p);

    // 4) normalized attention output
    outnorm_kernel<<<dim3(HW / 256, B_SZ * NHEAD), 256>>>(qkv_p, agg_p, vk_p, outn_p);

    // 5) out = x + W_proj @ outn : M=512, K=1024, N=4096, per batch
    gemm_tf32_kernel<<<dim3(HW / GBN, 512 / GBM, B_SZ), 256>>>(
        w_proj, outn_p, out, x, 512, 1024, HW);
}

// round 4
// speedup vs baseline: 1.5196x; 1.5196x over previous
#include <cuda_runtime.h>
#include <cstdint>

// Problem constants
#define B_SZ   4
#define C_IN   512
#define HW     4096
#define HH     64
#define WW     64
#define NCH3   1536
#define GROUPS 192
#define NHEAD  128
#define EPSF   1e-15f

// ---------------- scratch ----------------
__device__ float g_qkv [(long)B_SZ * NCH3 * HW];
__device__ float g_agg [(long)B_SZ * NCH3 * HW];
__device__ float g_outn[(long)B_SZ * 1024 * HW];
__device__ float g_vk  [B_SZ * NHEAD * 72];

// ---------------- helpers ----------------
__device__ __forceinline__ uint32_t f2tf32(float f) {
    uint32_t r; asm("cvt.rna.tf32.f32 %0, %1;" : "=r"(r) : "f"(f)); return r;
}
__device__ __forceinline__ void mma_tf32(float (&c)[4], const uint32_t (&a)[4], const uint32_t (&b)[2]) {
    asm volatile(
        "mma.sync.aligned.m16n8k8.row.col.f32.tf32.tf32.f32 "
        "{%0,%1,%2,%3}, {%4,%5,%6,%7}, {%8,%9}, {%0,%1,%2,%3};\n"
        : "+f"(c[0]), "+f"(c[1]), "+f"(c[2]), "+f"(c[3])
        : "r"(a[0]), "r"(a[1]), "r"(a[2]), "r"(a[3]), "r"(b[0]), "r"(b[1]));
}
__device__ __forceinline__ uint32_t smem_u32(const void* p) {
    uint32_t a;
    asm("{ .reg .u64 t; cvta.to.shared.u64 t, %1; cvt.u32.u64 %0, t; }" : "=r"(a) : "l"(p));
    return a;
}
__device__ __forceinline__ void cpasync16(uint32_t s, const void* g) {
    asm volatile("cp.async.cg.shared.global [%0], [%1], 16;" :: "r"(s), "l"(g));
}
__device__ __forceinline__ void cp_commit() {
    asm volatile("cp.async.commit_group;" ::: "memory");
}
__device__ __forceinline__ void cp_wait0() {
    asm volatile("cp.async.wait_group 0;" ::: "memory");
}

// ---------------- GEMM: C[b] = W[M,K] * X[b][K,N] (+Addend) ----------------
// CTA 128x128, BK=16, 8 warps (2m x 4n), warp tile 64x32.
// A smem: [128][20] f32 (row-major, pad->conflict-free frags)
// B smem: [16][136] f32
#define ASTRIDE 20
#define BSTRIDE 136
#define A_WORDS (128 * ASTRIDE)      // 2560
#define B_WORDS (16 * BSTRIDE)       // 2176
#define STAGE_WORDS (A_WORDS + B_WORDS)
#define SMEM_BYTES (2 * STAGE_WORDS * 4)   // 37888

__global__ void __launch_bounds__(256, 2)
gemm_tf32cp_kernel(const float* __restrict__ Wm, const float* __restrict__ Xm,
                   float* __restrict__ Cm, const float* __restrict__ Addend,
                   int M, int K, int N)
{
    extern __shared__ float smem[];

    int b  = blockIdx.z;
    const float* Xb = Xm + (long)b * K * N;
    float*       Cb = Cm + (long)b * M * N;
    const float* Ab = Addend ? (Addend + (long)b * M * N) : nullptr;

    int m0 = blockIdx.y * 128;
    int n0 = blockIdx.x * 128;

    int tid  = threadIdx.x;
    int lane = tid & 31, warp = tid >> 5;
    int wm = warp >> 2;          // 0..1
    int wn = warp & 3;           // 0..3
    int g = lane >> 2, t = lane & 3;
    int mbase = wm * 64, nbase = wn * 32;

    // load mappings (per thread: 2 A float4 + 2 B float4 per stage)
    int amA = tid >> 2;                 // 0..63  (first A chunk), +64 second
    int akA = (tid & 3) * 4;            // 0,4,8,12
    int bkB = tid >> 5;                 // 0..7  (first B chunk), +8 second
    int bnB = (tid & 31) * 4;           // 0..124

    uint32_t sbase = smem_u32(smem);
    uint32_t sA[2], sB[2];
    sA[0] = sbase;
    sB[0] = sbase + A_WORDS * 4;
    sA[1] = sbase + STAGE_WORDS * 4;
    sB[1] = sA[1] + A_WORDS * 4;

    const float* gA0 = &Wm[(long)(m0 + amA) * K + akA];
    const float* gA1 = &Wm[(long)(m0 + amA + 64) * K + akA];
    const float* gB0 = &Xb[(long)bkB * N + n0 + bnB];
    const float* gB1 = &Xb[(long)(bkB + 8) * N + n0 + bnB];

    uint32_t sAo0 = (amA * ASTRIDE + akA) * 4;
    uint32_t sAo1 = ((amA + 64) * ASTRIDE + akA) * 4;
    uint32_t sBo0 = (bkB * BSTRIDE + bnB) * 4;
    uint32_t sBo1 = ((bkB + 8) * BSTRIDE + bnB) * 4;

    float acc[4][4][4];
#pragma unroll
    for (int i = 0; i < 4; i++)
#pragma unroll
        for (int j = 0; j < 4; j++)
#pragma unroll
            for (int q = 0; q < 4; q++) acc[i][j][q] = 0.f;

    // prologue: stage 0
    cpasync16(sA[0] + sAo0, gA0);
    cpasync16(sA[0] + sAo1, gA1);
    cpasync16(sB[0] + sBo0, gB0);
    cpasync16(sB[0] + sBo1, gB1);
    cp_commit();

    int KT = K / 16;
    for (int kt = 0; kt < KT; kt++) {
        cp_wait0();
        __syncthreads();

        int p = kt & 1;
        if (kt + 1 < KT) {
            long ko = (long)(kt + 1) * 16;
            int q = p ^ 1;
            cpasync16(sA[q] + sAo0, gA0 + ko);
            cpasync16(sA[q] + sAo1, gA1 + ko);
            cpasync16(sB[q] + sBo0, gB0 + ko * N);
            cpasync16(sB[q] + sBo1, gB1 + ko * N);
            cp_commit();
        }

        const float* As = smem + p * STAGE_WORDS;             // [128][20]
        const float* Bs = smem + p * STAGE_WORDS + A_WORDS;   // [16][136]

#pragma unroll
        for (int k8 = 0; k8 < 16; k8 += 8) {
            uint32_t af[4][4], bf[4][2];
#pragma unroll
            for (int mi = 0; mi < 4; mi++) {
                int r0 = mbase + mi * 16 + g;
                af[mi][0] = f2tf32(As[r0 * ASTRIDE + k8 + t]);
                af[mi][1] = f2tf32(As[(r0 + 8) * ASTRIDE + k8 + t]);
                af[mi][2] = f2tf32(As[r0 * ASTRIDE + k8 + t + 4]);
                af[mi][3] = f2tf32(As[(r0 + 8) * ASTRIDE + k8 + t + 4]);
            }
#pragma unroll
            for (int ni = 0; ni < 4; ni++) {
                int c = nbase + ni * 8 + g;
                bf[ni][0] = f2tf32(Bs[(k8 + t) * BSTRIDE + c]);
                bf[ni][1] = f2tf32(Bs[(k8 + t + 4) * BSTRIDE + c]);
            }
#pragma unroll
            for (int mi = 0; mi < 4; mi++)
#pragma unroll
                for (int ni = 0; ni < 4; ni++)
                    mma_tf32(acc[mi][ni], af[mi], bf[ni]);
        }
        __syncthreads();
    }

    // epilogue
#pragma unroll
    for (int mi = 0; mi < 4; mi++) {
#pragma unroll
        for (int ni = 0; ni < 4; ni++) {
            int row = m0 + mbase + mi * 16 + g;
            int col = n0 + nbase + ni * 8 + 2 * t;
            float2 v0 = make_float2(acc[mi][ni][0], acc[mi][ni][1]);
            float2 v1 = make_float2(acc[mi][ni][2], acc[mi][ni][3]);
            long o0 = (long)row * N + col;
            long o1 = (long)(row + 8) * N + col;
            if (Ab) {
                float2 a0 = *(const float2*)&Ab[o0];
                float2 a1 = *(const float2*)&Ab[o1];
                v0.x += a0.x; v0.y += a0.y;
                v1.x += a1.x; v1.y += a1.y;
            }
            *(float2*)&Cb[o0] = v0;
            *(float2*)&Cb[o1] = v1;
        }
    }
}

// ---------------- fused depthwise 5x5 + grouped pointwise 8x8 ----------------
__global__ void __launch_bounds__(256)
dwpw_kernel(const float* __restrict__ qkv, const float* __restrict__ w_dw,
            const float* __restrict__ w_pw, float* __restrict__ agg)
{
    __shared__ float in_s[36][36];
    __shared__ float dw_s[8][1024];
    __shared__ float wpw_s[64];

    int tid = threadIdx.x;
    int tb  = blockIdx.x;
    int x0  = (tb & 1) * 32;
    int y0  = (tb >> 1) * 32;
    int grp = blockIdx.y;
    int b   = blockIdx.z;

    if (tid < 64) wpw_s[tid] = w_pw[(grp * 8 + (tid >> 3)) * 8 + (tid & 7)];

    for (int c = 0; c < 8; c++) {
        int ch = grp * 8 + c;
        const float* src = qkv + ((long)b * NCH3 + ch) * HW;
        __syncthreads();
        for (int i = tid; i < 36 * 36; i += 256) {
            int r = i / 36, cc = i % 36;
            int gy = y0 + r - 2, gx = x0 + cc - 2;
            float v = 0.f;
            if (gy >= 0 && gy < HH && gx >= 0 && gx < WW)
                v = src[gy * WW + gx];
            in_s[r][cc] = v;
        }
        float wreg[25];
#pragma unroll
        for (int j = 0; j < 25; j++) wreg[j] = __ldg(&w_dw[ch * 25 + j]);
        __syncthreads();
        for (int p = tid; p < 1024; p += 256) {
            int py = p >> 5, px = p & 31;
            float s = 0.f;
#pragma unroll
            for (int dy = 0; dy < 5; dy++)
#pragma unroll
                for (int dx = 0; dx < 5; dx++)
                    s += in_s[py + dy][px + dx] * wreg[dy * 5 + dx];
            dw_s[c][p] = s;
        }
    }
    __syncthreads();

    for (int p = tid; p < 1024; p += 256) {
        float din[8];
#pragma unroll
        for (int i = 0; i < 8; i++) din[i] = dw_s[i][p];
        int py = p >> 5, px = p & 31;
        long base = ((long)b * NCH3 + grp * 8) * HW + (long)(y0 + py) * WW + (x0 + px);
#pragma unroll
        for (int o = 0; o < 8; o++) {
            float s = 0.f;
#pragma unroll
            for (int i = 0; i < 8; i++) s += wpw_s[o * 8 + i] * din[i];
            agg[base + (long)o * HW] = s;
        }
    }
}

// ---------------- vk reduction ----------------
__global__ void __launch_bounds__(256)
vk_kernel(const float* __restrict__ qkv, const float* __restrict__ agg,
          float* __restrict__ vkout)
{
    int bh = blockIdx.x;
    int b = bh >> 7, h = bh & 127;
    const float* src = (h < 64)
        ? qkv + ((long)b * NCH3 + h * 24) * HW
        : agg + ((long)b * NCH3 + (h - 64) * 24) * HW;

    int tid = threadIdx.x, lane = tid & 31;
    float acc[72];
#pragma unroll
    for (int i = 0; i < 72; i++) acc[i] = 0.f;

    for (int n = tid; n < HW; n += 256) {
        float kv[8], vv[8];
#pragma unroll
        for (int e = 0; e < 8; e++) kv[e] = fmaxf(src[(long)(8 + e) * HW + n], 0.f);
#pragma unroll
        for (int d = 0; d < 8; d++) vv[d] = src[(long)(16 + d) * HW + n];
#pragma unroll
        for (int d = 0; d < 8; d++)
#pragma unroll
            for (int e = 0; e < 8; e++) acc[d * 8 + e] += vv[d] * kv[e];
#pragma unroll
        for (int e = 0; e < 8; e++) acc[64 + e] += kv[e];
    }
#pragma unroll
    for (int i = 0; i < 72; i++) {
#pragma unroll
        for (int off = 16; off > 0; off >>= 1)
            acc[i] += __shfl_xor_sync(0xFFFFFFFFu, acc[i], off);
    }
    __shared__ float red[72];
    if (tid < 72) red[tid] = 0.f;
    __syncthreads();
    if (lane == 0) {
#pragma unroll
        for (int i = 0; i < 72; i++) atomicAdd(&red[i], acc[i]);
    }
    __syncthreads();
    if (tid < 72) vkout[(long)bh * 72 + tid] = red[tid];
}

// ---------------- attention output + normalize ----------------
__global__ void __launch_bounds__(256)
outnorm_kernel(const float* __restrict__ qkv, const float* __restrict__ agg,
               const float* __restrict__ vkin, float* __restrict__ outn)
{
    int bh = blockIdx.y;
    int b = bh >> 7, h = bh & 127;
    const float* src = (h < 64)
        ? qkv + ((long)b * NCH3 + h * 24) * HW
        : agg + ((long)b * NCH3 + (h - 64) * 24) * HW;

    __shared__ float vks[72];
    int tid = threadIdx.x;
    if (tid < 72) vks[tid] = vkin[(long)bh * 72 + tid];
    __syncthreads();

    int n = blockIdx.x * 256 + tid;
    float q[8];
#pragma unroll
    for (int e = 0; e < 8; e++) q[e] = fmaxf(src[(long)e * HW + n], 0.f);

    float den = 0.f;
#pragma unroll
    for (int e = 0; e < 8; e++) den += vks[64 + e] * q[e];
    float inv = 1.f / (den + EPSF);

    long obase = ((long)b * 1024 + h * 8) * HW + n;
#pragma unroll
    for (int d = 0; d < 8; d++) {
        float num = 0.f;
#pragma unroll
        for (int e = 0; e < 8; e++) num += vks[d * 8 + e] * q[e];
        outn[obase + (long)d * HW] = num * inv;
    }
}

// ---------------- launch ----------------
extern "C" void kernel_launch(void* const* d_in, const int* in_sizes, int n_in,
                              void* d_out, int out_size)
{
    const float* x      = (const float*)d_in[0];
    const float* w_qkv  = (const float*)d_in[1];
    const float* w_dw   = (const float*)d_in[2];
    const float* w_pw   = (const float*)d_in[3];
    const float* w_proj = (const float*)d_in[4];
    float* out = (float*)d_out;

    float *qkv_p, *agg_p, *outn_p, *vk_p;
    cudaGetSymbolAddress((void**)&qkv_p,  g_qkv);
    cudaGetSymbolAddress((void**)&agg_p,  g_agg);
    cudaGetSymbolAddress((void**)&outn_p, g_outn);
    cudaGetSymbolAddress((void**)&vk_p,   g_vk);

    // 1) qkv = W_qkv @ x : M=1536, K=512
    gemm_tf32cp_kernel<<<dim3(HW / 128, NCH3 / 128, B_SZ), 256, SMEM_BYTES>>>(
        w_qkv, x, qkv_p, nullptr, NCH3, C_IN, HW);

    // 2) agg = grouped_pw(depthwise5x5(qkv))
    dwpw_kernel<<<dim3(4, GROUPS, B_SZ), 256>>>(qkv_p, w_dw, w_pw, agg_p);

    // 3) vk reductions
    vk_kernel<<<B_SZ * NHEAD, 256>>>(qkv_p, agg_p, vk_p);

    // 4) normalized attention output
    outnorm_kernel<<<dim3(HW / 256, B_SZ * NHEAD), 256>>>(qkv_p, agg_p, vk_p, outn_p);

    // 5) out = x + W_proj @ outn : M=512, K=1024
    gemm_tf32cp_kernel<<<dim3(HW / 128, 512 / 128, B_SZ), 256, SMEM_BYTES>>>(
        w_proj, outn_p, out, x, 512, 1024, HW);
}

// round 5
// speedup vs baseline: 1.9430x; 1.2786x over previous
#include <cuda_runtime.h>
#include <cuda_fp16.h>
#include <cstdint>

// Problem constants
#define B_SZ   4
#define C_IN   512
#define HW     4096
#define HH     64
#define WW     64
#define NCH3   1536
#define GROUPS 192
#define NHEAD  128
#define EPSF   1e-15f

// ---------------- scratch ----------------
__device__ float  g_qkv[(long)B_SZ * NCH3 * HW];
__device__ float  g_agg[(long)B_SZ * NCH3 * HW];
__device__ float  g_vk [B_SZ * NHEAD * 72];
__device__ __half g_xt1[(long)B_SZ * HW * 512];    // x transposed  [b][n][k]
__device__ __half g_xt2[(long)B_SZ * HW * 1024];   // outn          [b][n][k]
__device__ __half g_wh1[NCH3 * 512];               // w_qkv fp16
__device__ __half g_wh2[512 * 1024];               // w_proj fp16

// ---------------- helpers ----------------
__device__ __forceinline__ void mma_f16(float (&c)[4], const uint32_t (&a)[4], const uint32_t (&b)[2]) {
    asm volatile(
        "mma.sync.aligned.m16n8k16.row.col.f32.f16.f16.f32 "
        "{%0,%1,%2,%3}, {%4,%5,%6,%7}, {%8,%9}, {%0,%1,%2,%3};\n"
        : "+f"(c[0]), "+f"(c[1]), "+f"(c[2]), "+f"(c[3])
        : "r"(a[0]), "r"(a[1]), "r"(a[2]), "r"(a[3]), "r"(b[0]), "r"(b[1]));
}
__device__ __forceinline__ uint32_t smem_u32(const void* p) {
    uint32_t a;
    asm("{ .reg .u64 t; cvta.to.shared.u64 t, %1; cvt.u32.u64 %0, t; }" : "=r"(a) : "l"(p));
    return a;
}
__device__ __forceinline__ void cpasync16(uint32_t s, const void* g) {
    asm volatile("cp.async.cg.shared.global [%0], [%1], 16;" :: "r"(s), "l"(g));
}
__device__ __forceinline__ void cp_commit() { asm volatile("cp.async.commit_group;" ::: "memory"); }
__device__ __forceinline__ void cp_wait0()  { asm volatile("cp.async.wait_group 0;" ::: "memory"); }

__device__ __forceinline__ uint32_t h2pack(float a, float b) {
    __half2 h = __floats2half2_rn(a, b);
    return *(uint32_t*)&h;
}

// ---------------- pre-pass: f32 -> fp16 weight convert (row-major preserved) ----------------
__global__ void __launch_bounds__(256)
convert_w_kernel(const float* __restrict__ W, __half* __restrict__ Wh)
{
    long i = ((long)blockIdx.x * 256 + threadIdx.x) * 8;
    float4 v0 = *(const float4*)&W[i];
    float4 v1 = *(const float4*)&W[i + 4];
    uint4 o;
    o.x = h2pack(v0.x, v0.y); o.y = h2pack(v0.z, v0.w);
    o.z = h2pack(v1.x, v1.y); o.w = h2pack(v1.z, v1.w);
    *(uint4*)&Wh[i] = o;
}

// ---------------- pre-pass: transpose x [b][K][4096] -> Xt [b][n][K] fp16 ----------------
__global__ void __launch_bounds__(256)
transpose_x_kernel(const float* __restrict__ X, __half* __restrict__ Xt, int K)
{
    __shared__ float ts[64][65];
    int n0 = blockIdx.x * 64, k0 = blockIdx.y * 64, b = blockIdx.z;
    int tid = threadIdx.x;
    const float* Xb = X + (long)b * K * HW;
#pragma unroll
    for (int i = 0; i < 16; i++) {
        int idx = tid + i * 256;
        int k = idx >> 6, n = idx & 63;
        ts[k][n] = Xb[(long)(k0 + k) * HW + n0 + n];
    }
    __syncthreads();
    __half* Xo = Xt + (long)b * HW * K;
#pragma unroll
    for (int i = 0; i < 4; i++) {
        int c = tid + i * 256;            // 1024 chunks of 4 halves
        int n = c >> 4, kc = (c & 15) * 4;
        uint2 o;
        o.x = h2pack(ts[kc + 0][n], ts[kc + 1][n]);
        o.y = h2pack(ts[kc + 2][n], ts[kc + 3][n]);
        *(uint2*)&Xo[(long)(n0 + n) * K + k0 + kc] = o;
    }
}

// ---------------- fp16 GEMM: C[b][M,4096] = W[M,K] * Xt[b][:,K]^T (+Addend) ----------------
// CTA 128x128, BK=32, 8 warps (2m x 4n), warp tile 64x32.
// smem per stage: A 128 rows x 20 words, B 128 rows x 20 words (row = 32 fp16 + pad)
#define S_WORDS 20
#define HALF_STAGE_WORDS (128 * S_WORDS)          // 2560 (A), then B
#define STAGE_WORDS (2 * HALF_STAGE_WORDS)        // 5120
#define STAGE_BYTES (STAGE_WORDS * 4)             // 20480
#define GSMEM_BYTES (2 * STAGE_BYTES)             // 40960

__global__ void __launch_bounds__(256, 2)
gemm_f16_kernel(const __half* __restrict__ Wh, const __half* __restrict__ Xt,
                float* __restrict__ Cm, const float* __restrict__ Addend,
                int M, int K)
{
    extern __shared__ float smem[];

    int b  = blockIdx.z;
    const __half* Xb = Xt + (long)b * HW * K;
    float*        Cb = Cm + (long)b * M * HW;
    const float*  Ab = Addend ? (Addend + (long)b * M * HW) : nullptr;

    int m0 = blockIdx.y * 128;
    int n0 = blockIdx.x * 128;

    int tid  = threadIdx.x;
    int lane = tid & 31, warp = tid >> 5;
    int wm = warp >> 2, wn = warp & 3;
    int g = lane >> 2, t4 = lane & 3;
    int mbase = wm * 64, nbase = wn * 32;

    // cp.async mapping: chunk c in [0,512): row=c>>2, part=c&3 (8 halves per chunk)
    int rowL = tid >> 2, partL = tid & 3;
    const __half* gA0 = Wh + (long)(m0 + rowL) * K + partL * 8;
    const __half* gA1 = gA0 + (long)64 * K;
    const __half* gB0 = Xb + (long)(n0 + rowL) * K + partL * 8;
    const __half* gB1 = gB0 + (long)64 * K;

    uint32_t sbase = smem_u32(smem);
    uint32_t oA0 = (rowL * S_WORDS + partL * 4) * 4;
    uint32_t oA1 = oA0 + 64 * S_WORDS * 4;
    uint32_t oB0 = HALF_STAGE_WORDS * 4 + oA0;
    uint32_t oB1 = HALF_STAGE_WORDS * 4 + oA1;

    float acc[4][4][4];
#pragma unroll
    for (int i = 0; i < 4; i++)
#pragma unroll
        for (int j = 0; j < 4; j++)
#pragma unroll
            for (int q = 0; q < 4; q++) acc[i][j][q] = 0.f;

    // prologue: stage 0
    cpasync16(sbase + oA0, gA0);
    cpasync16(sbase + oA1, gA1);
    cpasync16(sbase + oB0, gB0);
    cpasync16(sbase + oB1, gB1);
    cp_commit();

    int KT = K / 32;
    for (int kt = 0; kt < KT; kt++) {
        cp_wait0();
        __syncthreads();

        int p = kt & 1;
        if (kt + 1 < KT) {
            long ko = (long)(kt + 1) * 32;      // halves
            uint32_t sq = sbase + (p ^ 1) * STAGE_BYTES;
            cpasync16(sq + oA0, gA0 + ko);
            cpasync16(sq + oA1, gA1 + ko);
            cpasync16(sq + oB0, gB0 + ko);
            cpasync16(sq + oB1, gB1 + ko);
            cp_commit();
        }

        const uint32_t* As = (const uint32_t*)smem + p * STAGE_WORDS;
        const uint32_t* Bs = As + HALF_STAGE_WORDS;

#pragma unroll
        for (int j = 0; j < 2; j++) {           // two k16 per stage
            int j8 = j * 8;
            uint32_t af[4][4], bf[4][2];
#pragma unroll
            for (int mi = 0; mi < 4; mi++) {
                int r0 = mbase + mi * 16 + g;
                const uint32_t* a0 = As + r0 * S_WORDS + j8 + t4;
                af[mi][0] = a0[0];
                af[mi][1] = a0[8 * S_WORDS];
                af[mi][2] = a0[4];
                af[mi][3] = a0[8 * S_WORDS + 4];
            }
#pragma unroll
            for (int ni = 0; ni < 4; ni++) {
                int c = nbase + ni * 8 + g;
                const uint32_t* b0 = Bs + c * S_WORDS + j8 + t4;
                bf[ni][0] = b0[0];
                bf[ni][1] = b0[4];
            }
#pragma unroll
            for (int mi = 0; mi < 4; mi++)
#pragma unroll
                for (int ni = 0; ni < 4; ni++)
                    mma_f16(acc[mi][ni], af[mi], bf[ni]);
        }
        __syncthreads();
    }

    // epilogue
#pragma unroll
    for (int mi = 0; mi < 4; mi++) {
#pragma unroll
        for (int ni = 0; ni < 4; ni++) {
            int row = m0 + mbase + mi * 16 + g;
            int col = n0 + nbase + ni * 8 + 2 * t4;
            float2 v0 = make_float2(acc[mi][ni][0], acc[mi][ni][1]);
            float2 v1 = make_float2(acc[mi][ni][2], acc[mi][ni][3]);
            long o0 = (long)row * HW + col;
            long o1 = (long)(row + 8) * HW + col;
            if (Ab) {
                float2 a0 = *(const float2*)&Ab[o0];
                float2 a1 = *(const float2*)&Ab[o1];
                v0.x += a0.x; v0.y += a0.y;
                v1.x += a1.x; v1.y += a1.y;
            }
            *(float2*)&Cb[o0] = v0;
            *(float2*)&Cb[o1] = v1;
        }
    }
}

// ---------------- fused depthwise 5x5 + grouped pointwise 8x8 ----------------
__global__ void __launch_bounds__(256)
dwpw_kernel(const float* __restrict__ qkv, const float* __restrict__ w_dw,
            const float* __restrict__ w_pw, float* __restrict__ agg)
{
    __shared__ float in_s[36][36];
    __shared__ float dw_s[8][1024];
    __shared__ float wpw_s[64];

    int tid = threadIdx.x;
    int tb  = blockIdx.x;
    int x0  = (tb & 1) * 32;
    int y0  = (tb >> 1) * 32;
    int grp = blockIdx.y;
    int b   = blockIdx.z;

    if (tid < 64) wpw_s[tid] = w_pw[(grp * 8 + (tid >> 3)) * 8 + (tid & 7)];

    for (int c = 0; c < 8; c++) {
        int ch = grp * 8 + c;
        const float* src = qkv + ((long)b * NCH3 + ch) * HW;
        __syncthreads();
        for (int i = tid; i < 36 * 36; i += 256) {
            int r = i / 36, cc = i % 36;
            int gy = y0 + r - 2, gx = x0 + cc - 2;
            float v = 0.f;
            if (gy >= 0 && gy < HH && gx >= 0 && gx < WW)
                v = src[gy * WW + gx];
            in_s[r][cc] = v;
        }
        float wreg[25];
#pragma unroll
        for (int j = 0; j < 25; j++) wreg[j] = __ldg(&w_dw[ch * 25 + j]);
        __syncthreads();
        for (int p = tid; p < 1024; p += 256) {
            int py = p >> 5, px = p & 31;
            float s = 0.f;
#pragma unroll
            for (int dy = 0; dy < 5; dy++)
#pragma unroll
                for (int dx = 0; dx < 5; dx++)
                    s += in_s[py + dy][px + dx] * wreg[dy * 5 + dx];
            dw_s[c][p] = s;
        }
    }
    __syncthreads();

    for (int p = tid; p < 1024; p += 256) {
        float din[8];
#pragma unroll
        for (int i = 0; i < 8; i++) din[i] = dw_s[i][p];
        int py = p >> 5, px = p & 31;
        long base = ((long)b * NCH3 + grp * 8) * HW + (long)(y0 + py) * WW + (x0 + px);
#pragma unroll
        for (int o = 0; o < 8; o++) {
            float s = 0.f;
#pragma unroll
            for (int i = 0; i < 8; i++) s += wpw_s[o * 8 + i] * din[i];
            agg[base + (long)o * HW] = s;
        }
    }
}

// ---------------- vk reduction ----------------
__global__ void __launch_bounds__(256)
vk_kernel(const float* __restrict__ qkv, const float* __restrict__ agg,
          float* __restrict__ vkout)
{
    int bh = blockIdx.x;
    int b = bh >> 7, h = bh & 127;
    const float* src = (h < 64)
        ? qkv + ((long)b * NCH3 + h * 24) * HW
        : agg + ((long)b * NCH3 + (h - 64) * 24) * HW;

    int tid = threadIdx.x, lane = tid & 31;
    float acc[72];
#pragma unroll
    for (int i = 0; i < 72; i++) acc[i] = 0.f;

    for (int n = tid; n < HW; n += 256) {
        float kv[8], vv[8];
#pragma unroll
        for (int e = 0; e < 8; e++) kv[e] = fmaxf(src[(long)(8 + e) * HW + n], 0.f);
#pragma unroll
        for (int d = 0; d < 8; d++) vv[d] = src[(long)(16 + d) * HW + n];
#pragma unroll
        for (int d = 0; d < 8; d++)
#pragma unroll
            for (int e = 0; e < 8; e++) acc[d * 8 + e] += vv[d] * kv[e];
#pragma unroll
        for (int e = 0; e < 8; e++) acc[64 + e] += kv[e];
    }
#pragma unroll
    for (int i = 0; i < 72; i++) {
#pragma unroll
        for (int off = 16; off > 0; off >>= 1)
            acc[i] += __shfl_xor_sync(0xFFFFFFFFu, acc[i], off);
    }
    __shared__ float red[72];
    if (tid < 72) red[tid] = 0.f;
    __syncthreads();
    if (lane == 0) {
#pragma unroll
        for (int i = 0; i < 72; i++) atomicAdd(&red[i], acc[i]);
    }
    __syncthreads();
    if (tid < 72) vkout[(long)bh * 72 + tid] = red[tid];
}

// ---------------- attention output + normalize -> fp16 [b][n][k] for GEMM2 ----------------
__global__ void __launch_bounds__(256)
outnorm_kernel(const float* __restrict__ qkv, const float* __restrict__ agg,
               const float* __restrict__ vkin, __half* __restrict__ xt2)
{
    int bh = blockIdx.y;
    int b = bh >> 7, h = bh & 127;
    const float* src = (h < 64)
        ? qkv + ((long)b * NCH3 + h * 24) * HW
        : agg + ((long)b * NCH3 + (h - 64) * 24) * HW;

    __shared__ float vks[72];
    int tid = threadIdx.x;
    if (tid < 72) vks[tid] = vkin[(long)bh * 72 + tid];
    __syncthreads();

    int n = blockIdx.x * 256 + tid;
    float q[8];
#pragma unroll
    for (int e = 0; e < 8; e++) q[e] = fmaxf(src[(long)e * HW + n], 0.f);

    float den = 0.f;
#pragma unroll
    for (int e = 0; e < 8; e++) den += vks[64 + e] * q[e];
    float inv = 1.f / (den + EPSF);

    float outv[8];
#pragma unroll
    for (int d = 0; d < 8; d++) {
        float num = 0.f;
#pragma unroll
        for (int e = 0; e < 8; e++) num += vks[d * 8 + e] * q[e];
        outv[d] = num * inv;
    }

    uint4 o;
    o.x = h2pack(outv[0], outv[1]);
    o.y = h2pack(outv[2], outv[3]);
    o.z = h2pack(outv[4], outv[5]);
    o.w = h2pack(outv[6], outv[7]);
    *(uint4*)&xt2[((long)b * HW + n) * 1024 + h * 8] = o;
}

// ---------------- launch ----------------
extern "C" void kernel_launch(void* const* d_in, const int* in_sizes, int n_in,
                              void* d_out, int out_size)
{
    const float* x      = (const float*)d_in[0];
    const float* w_qkv  = (const float*)d_in[1];
    const float* w_dw   = (const float*)d_in[2];
    const float* w_pw   = (const float*)d_in[3];
    const float* w_proj = (const float*)d_in[4];
    float* out = (float*)d_out;

    float *qkv_p, *agg_p, *vk_p;
    __half *xt1, *xt2, *wh1, *wh2;
    cudaGetSymbolAddress((void**)&qkv_p, g_qkv);
    cudaGetSymbolAddress((void**)&agg_p, g_agg);
    cudaGetSymbolAddress((void**)&vk_p,  g_vk);
    cudaGetSymbolAddress((void**)&xt1,   g_xt1);
    cudaGetSymbolAddress((void**)&xt2,   g_xt2);
    cudaGetSymbolAddress((void**)&wh1,   g_wh1);
    cudaGetSymbolAddress((void**)&wh2,   g_wh2);

    // pre-passes
    convert_w_kernel<<<NCH3 * 512 / 2048, 256>>>(w_qkv, wh1);
    convert_w_kernel<<<512 * 1024 / 2048, 256>>>(w_proj, wh2);
    transpose_x_kernel<<<dim3(HW / 64, 512 / 64, B_SZ), 256>>>(x, xt1, 512);

    // 1) qkv = W_qkv @ x : M=1536, K=512
    gemm_f16_kernel<<<dim3(HW / 128, NCH3 / 128, B_SZ), 256, GSMEM_BYTES>>>(
        wh1, xt1, qkv_p, nullptr, NCH3, 512);

    // 2) agg = grouped_pw(depthwise5x5(qkv))
    dwpw_kernel<<<dim3(4, GROUPS, B_SZ), 256>>>(qkv_p, w_dw, w_pw, agg_p);

    // 3) vk reductions
    vk_kernel<<<B_SZ * NHEAD, 256>>>(qkv_p, agg_p, vk_p);

    // 4) attention normalize -> fp16 B operand for GEMM2
    outnorm_kernel<<<dim3(HW / 256, B_SZ * NHEAD), 256>>>(qkv_p, agg_p, vk_p, xt2);

    // 5) out = x + W_proj @ outn : M=512, K=1024
    gemm_f16_kernel<<<dim3(HW / 128, 512 / 128, B_SZ), 256, GSMEM_BYTES>>>(
        wh2, xt2, out, x, 512, 1024);
}